// round 14
// baseline (speedup 1.0000x reference)
#include <cuda_runtime.h>
#include <cuda_fp16.h>
#include <cstdint>

// ===========================================================================
// Problem constants
// ===========================================================================
#define B_    8
#define NQ    1024
#define NK    1024
#define D_    512
#define H_    8
#define HD    64
#define INNER 512
#define KV_W  1024
#define SCALE 0.125f
#define LOG2E 1.44269504f
#define MROWS (B_ * NQ)          // 8192

// ===========================================================================
// Scratch (__device__ globals)
// ===========================================================================
__device__ __align__(16) __half g_qh [MROWS * INNER];
__device__ __align__(16) __half g_kvh[MROWS * KV_W];
__device__ __align__(16) __half g_ao [MROWS * INNER];

__device__ __align__(16) __half g_xh [MROWS * D_];
__device__ __align__(16) __half g_ch [MROWS * D_];
__device__ __align__(16) __half g_wqt [INNER * D_];
__device__ __align__(16) __half g_wkvt[KV_W * D_];
__device__ __align__(16) __half g_wot [D_ * INNER];

// ===========================================================================
// PTX helpers (compute_103-safe)
// ===========================================================================
__device__ __forceinline__ uint32_t smem_u32(const void* p) {
    uint32_t a;
    asm("{ .reg .u64 t; cvta.to.shared.u64 t, %1; cvt.u32.u64 %0, t; }"
        : "=r"(a) : "l"(p));
    return a;
}
#define CP16(dst_u32, src_ptr) \
    asm volatile("cp.async.cg.shared.global [%0], [%1], 16;" \
                 :: "r"(dst_u32), "l"(src_ptr) : "memory")
#define CP_COMMIT() asm volatile("cp.async.commit_group;" ::: "memory")
#define CP_WAIT(n)  asm volatile("cp.async.wait_group %0;" :: "n"(n) : "memory")

#define LDSM4(r0, r1, r2, r3, addr) \
    asm volatile("ldmatrix.sync.aligned.m8n8.x4.shared.b16 {%0,%1,%2,%3}, [%4];" \
                 : "=r"(r0), "=r"(r1), "=r"(r2), "=r"(r3) : "r"(addr))
#define LDSM4T(r0, r1, r2, r3, addr) \
    asm volatile("ldmatrix.sync.aligned.m8n8.x4.trans.shared.b16 {%0,%1,%2,%3}, [%4];" \
                 : "=r"(r0), "=r"(r1), "=r"(r2), "=r"(r3) : "r"(addr))

#define MMA_FP(d, a, b) \
    asm volatile("mma.sync.aligned.m16n8k16.row.col.f32.f16.f16.f32 " \
                 "{%0,%1,%2,%3},{%4,%5,%6,%7},{%8,%9},{%0,%1,%2,%3};" \
                 : "+f"((d)[0]), "+f"((d)[1]), "+f"((d)[2]), "+f"((d)[3]) \
                 : "r"((a)[0]), "r"((a)[1]), "r"((a)[2]), "r"((a)[3]), \
                   "r"((b)[0]), "r"((b)[1]))

#define H2EX2(d, s) \
    asm("ex2.approx.f16x2 %0, %1;" : "=r"(d) : "r"(s))

__device__ __forceinline__ uint32_t pack_h2(float lo, float hi) {
    const __half2 h = __floats2half2_rn(lo, hi);
    return *(const uint32_t*)&h;
}

// ===========================================================================
// Common tile constants
// ===========================================================================
#define KC    32
#define ROWB  80
#define ARR_B (128 * ROWB)             // 10240
#define STG16_B  (2 * ARR_B)           // 20480
#define SM16_TOT (2 * STG16_B)         // 40960

// ===========================================================================
// Plain fp16 GEMM core. MODE 0: fp32 out + bias.  MODE 1: fp16 out * oscale.
// ===========================================================================
template <int MODE>
__device__ __forceinline__ void gemm16_core(
    const __half* __restrict__ A, const __half* __restrict__ B,
    const float* __restrict__ bias, void* __restrict__ Cout,
    int N, int K, int m0, int n0, float oscale, char* sm)
{
    const uint32_t sb = smem_u32(sm);
    const int tid = threadIdx.x, lane = tid & 31, warp = tid >> 5;
    const int wm = (warp >> 2) * 64, wn = (warp & 3) * 32;

    const int ldrow = tid >> 1;
    const int ldcb  = (tid & 1) * 32;

    auto stage_load = [&](int s, int k0) {
        const uint32_t so = (uint32_t)(s * STG16_B + ldrow * ROWB + ldcb);
        const size_t ga = ((size_t)(m0 + ldrow) * K + k0) * 2 + ldcb;
        const size_t gb = ((size_t)(n0 + ldrow) * K + k0) * 2 + ldcb;
        CP16(sb + so,              (const char*)A + ga);
        CP16(sb + so + 16,         (const char*)A + ga + 16);
        CP16(sb + so + ARR_B,      (const char*)B + gb);
        CP16(sb + so + ARR_B + 16, (const char*)B + gb + 16);
    };

    float acc[4][4][4] = {};
    const int nch = K / KC;
    stage_load(0, 0);
    CP_COMMIT();

    for (int ch = 0; ch < nch; ch++) {
        if (ch + 1 < nch) {
            stage_load((ch + 1) & 1, (ch + 1) * KC);
            CP_COMMIT();
            CP_WAIT(1);
        } else {
            CP_WAIT(0);
        }
        __syncthreads();

        const uint32_t abase = sb + (ch & 1) * STG16_B;
        const uint32_t bbase = abase + ARR_B;

        #pragma unroll
        for (int ks = 0; ks < 2; ks++) {
            const int kb = ks * 32;

            uint32_t af[4][4];
            const uint32_t arow = (uint32_t)(wm + (lane & 15));
            const uint32_t akb  = (uint32_t)(kb + (lane >> 4) * 16);
            #pragma unroll
            for (int mi = 0; mi < 4; mi++) {
                const uint32_t ad = abase + (arow + mi * 16) * ROWB + akb;
                LDSM4(af[mi][0], af[mi][1], af[mi][2], af[mi][3], ad);
            }

            uint32_t bf[4][2];
            const uint32_t brow = (uint32_t)(wn + (lane & 7) + ((lane >> 4) & 1) * 8);
            const uint32_t bkb  = (uint32_t)(kb + ((lane >> 3) & 1) * 16);
            #pragma unroll
            for (int nq = 0; nq < 2; nq++) {
                const uint32_t bd = bbase + (brow + nq * 16) * ROWB + bkb;
                uint32_t r0, r1, r2, r3;
                LDSM4(r0, r1, r2, r3, bd);
                bf[nq * 2][0] = r0; bf[nq * 2][1] = r1;
                bf[nq * 2 + 1][0] = r2; bf[nq * 2 + 1][1] = r3;
            }

            #pragma unroll
            for (int mi = 0; mi < 4; mi++)
                #pragma unroll
                for (int ni = 0; ni < 4; ni++)
                    MMA_FP(acc[mi][ni], af[mi], bf[ni]);
        }
        __syncthreads();
    }

    #pragma unroll
    for (int mi = 0; mi < 4; mi++) {
        const int r = m0 + wm + mi * 16 + (lane >> 2);
        #pragma unroll
        for (int ni = 0; ni < 4; ni++) {
            const int c = n0 + wn + ni * 8 + (lane & 3) * 2;
            if (MODE == 0) {
                float* C = (float*)Cout;
                const float2 b2 = *(const float2*)(bias + c);
                *(float2*)(C + (size_t)r * N + c) =
                    make_float2(acc[mi][ni][0] + b2.x, acc[mi][ni][1] + b2.y);
                *(float2*)(C + (size_t)(r + 8) * N + c) =
                    make_float2(acc[mi][ni][2] + b2.x, acc[mi][ni][3] + b2.y);
            } else {
                __half* C = (__half*)Cout;
                *(__half2*)(C + (size_t)r * N + c) =
                    __floats2half2_rn(acc[mi][ni][0] * oscale, acc[mi][ni][1] * oscale);
                *(__half2*)(C + (size_t)(r + 8) * N + c) =
                    __floats2half2_rn(acc[mi][ni][2] * oscale, acc[mi][ni][3] * oscale);
            }
        }
    }
}

// fused q + kv projections
__global__ __launch_bounds__(256) void gemm_qkv16(
    const __half* __restrict__ xh, const __half* __restrict__ ch,
    const __half* __restrict__ wqt, const __half* __restrict__ wkvt,
    __half* __restrict__ qh, __half* __restrict__ kvh)
{
    extern __shared__ char sm[];
    const int m0 = blockIdx.y * 128;
    if (blockIdx.x < INNER / 128)
        gemm16_core<1>(xh, wqt, nullptr, qh, INNER, D_, m0, blockIdx.x * 128,
                       SCALE * LOG2E, sm);
    else
        gemm16_core<1>(ch, wkvt, nullptr, kvh, KV_W, D_, m0,
                       (blockIdx.x - INNER / 128) * 128, 1.0f, sm);
}

// output projection
__global__ __launch_bounds__(256) void gemm_out16(
    const __half* __restrict__ ao, const __half* __restrict__ wot,
    const float* __restrict__ bias, float* __restrict__ C)
{
    extern __shared__ char sm[];
    gemm16_core<0>(ao, wot, bias, C, D_, INNER,
                   blockIdx.y * 128, blockIdx.x * 128, 1.0f, sm);
}

// ===========================================================================
// Fused conversions: x/context elementwise + 3 weight transposes, ONE launch.
//   blocks [0, 8192)    : x (first 4096) / context (next 4096) fp32->fp16
//   blocks [8192, 9216) : weight transpose tiles
// ===========================================================================
__global__ __launch_bounds__(256) void conv_all(
    const float* __restrict__ x, __half* __restrict__ xh,
    const float* __restrict__ ctx, __half* __restrict__ ch,
    const float* __restrict__ Wq, const float* __restrict__ Wkv,
    const float* __restrict__ Wo,
    __half* __restrict__ wqt, __half* __restrict__ wkvt, __half* __restrict__ wot)
{
    const int tid = threadIdx.x;
    int bid = blockIdx.x;
    const int NX4 = MROWS * D_ / 4;                  // 1,048,576 float4s
    if (bid < 8192) {
        const bool second = bid >= 4096;
        const float* in = second ? ctx : x;
        __half* outp = second ? ch : xh;
        const int i = (second ? bid - 4096 : bid) * 256 + tid;
        if (i < NX4) {
            const float4 v = *((const float4*)in + i);
            __half h[4];
            h[0] = __float2half_rn(v.x); h[1] = __float2half_rn(v.y);
            h[2] = __float2half_rn(v.z); h[3] = __float2half_rn(v.w);
            *((uint2*)outp + i) = *(const uint2*)h;
        }
        return;
    }
    bid -= 8192;
    __shared__ float t[32][33];
    const int tx = tid & 31, ty = tid >> 5;          // 32x8
    const float* W; __half* WT; int K, N, rel;
    if (bid < 256)      { W = Wq;  WT = wqt;  K = D_;    N = INNER; rel = bid; }
    else if (bid < 768) { W = Wkv; WT = wkvt; K = D_;    N = KV_W;  rel = bid - 256; }
    else                { W = Wo;  WT = wot;  K = INNER; N = D_;    rel = bid - 768; }
    const int nbx = N / 32;
    const int c0 = (rel % nbx) * 32, r0 = (rel / nbx) * 32;

    #pragma unroll
    for (int j = 0; j < 4; j++)
        t[ty + 8 * j][tx] = W[(size_t)(r0 + ty + 8 * j) * N + c0 + tx];
    __syncthreads();
    #pragma unroll
    for (int j = 0; j < 4; j++)
        WT[(size_t)(c0 + ty + 8 * j) * K + r0 + tx] =
            __float2half_rn(t[tx][ty + 8 * j]);
}

// ===========================================================================
// Tensor-core flash attention (128 q-rows, 8 warps).
// Register-trimmed: Q fragments reloaded per-ks from SMEM; 3 CTAs/SM target.
// Softmax: p = exp2(s) fp16x2; row sums via ones-MMA.
// ===========================================================================
#define QROWB 144
#define QS_B  (128 * QROWB)
#define KVSTG (2 * 64 * QROWB)
#define ATT_SMEM (QS_B + 2 * KVSTG)

__global__ __launch_bounds__(256, 3) void attn_mma(
    const __half* __restrict__ qh, const __half* __restrict__ kvh,
    __half* __restrict__ ao)
{
    extern __shared__ char sm[];
    const uint32_t sb = smem_u32(sm);
    const int tid = threadIdx.x, lane = tid & 31, warp = tid >> 5;
    const int bh = blockIdx.y, b = bh >> 3, h = bh & 7;
    const int q0 = blockIdx.x * 128;

    #pragma unroll
    for (int r = 0; r < 4; r++) {
        const int cid = tid + r * 256;
        const int row = cid >> 3, ck = cid & 7;
        const char* src = (const char*)(qh + (size_t)(b * NQ + q0 + row) * INNER + h * HD) + ck * 16;
        CP16(sb + row * QROWB + ck * 16, src);
    }
    CP_COMMIT();

    const __half* kbase = kvh + (size_t)(b * NK) * KV_W + h * HD;
    const __half* vbase = kbase + INNER;
    auto kv_stage = [&](int s, int t) {
        const uint32_t so = sb + QS_B + s * KVSTG;
        #pragma unroll
        for (int r = 0; r < 2; r++) {
            const int cid = tid + r * 256;
            const int row = cid >> 3, ck = cid & 7;
            const size_t go = ((size_t)(t * 64 + row) * KV_W + ck * 8) * 2;
            CP16(so + row * QROWB + ck * 16,              (const char*)kbase + go);
            CP16(so + 64 * QROWB + row * QROWB + ck * 16, (const char*)vbase + go);
        }
    };
    kv_stage(0, 0);
    CP_COMMIT();

    CP_WAIT(1);
    __syncthreads();

    const uint32_t qb = sb + warp * 16 * QROWB
                      + (lane & 15) * QROWB + (lane >> 4) * 16;

    const uint32_t ONES2 = 0x3C003C00u;
    uint32_t onesf[2] = {ONES2, ONES2};

    float o[8][4] = {};
    float lacc[4] = {};

    for (int t = 0; t < 16; t++) {
        if (t + 1 < 16) {
            kv_stage((t + 1) & 1, t + 1);
            CP_COMMIT();
            CP_WAIT(1);
        } else {
            CP_WAIT(0);
        }
        __syncthreads();

        const uint32_t kbs = sb + QS_B + (t & 1) * KVSTG;
        const uint32_t vbs = kbs + 64 * QROWB;

        // ---- S = Q @ K^T  (Q fragment reloaded per ks: 4 live regs) ----
        float s[8][4] = {};
        #pragma unroll
        for (int ks = 0; ks < 4; ks++) {
            uint32_t qf[4];
            LDSM4(qf[0], qf[1], qf[2], qf[3], qb + ks * 32);
            #pragma unroll
            for (int nq = 0; nq < 4; nq++) {
                const uint32_t bd = kbs
                    + (nq * 16 + (lane & 7) + ((lane >> 4) & 1) * 8) * QROWB
                    + ks * 32 + ((lane >> 3) & 1) * 16;
                uint32_t r0, r1, r2, r3;
                LDSM4(r0, r1, r2, r3, bd);
                uint32_t bA[2] = {r0, r1}, bB[2] = {r2, r3};
                MMA_FP(s[nq * 2],     qf, bA);
                MMA_FP(s[nq * 2 + 1], qf, bB);
            }
        }

        // ---- p = exp2(s) fp16x2 (in-place into s storage footprint) ----
        uint32_t p[8][2];
        #pragma unroll
        for (int j = 0; j < 8; j++) {
            uint32_t t0 = pack_h2(s[j][0], s[j][1]);
            uint32_t t1 = pack_h2(s[j][2], s[j][3]);
            H2EX2(p[j][0], t0);
            H2EX2(p[j][1], t1);
        }

        // ---- O += P @ V ; l += P @ ones ----
        #pragma unroll
        for (int ks = 0; ks < 4; ks++) {
            uint32_t a[4];
            a[0] = p[2 * ks][0];
            a[1] = p[2 * ks][1];
            a[2] = p[2 * ks + 1][0];
            a[3] = p[2 * ks + 1][1];
            MMA_FP(lacc, a, onesf);
            #pragma unroll
            for (int nb = 0; nb < 4; nb++) {
                const uint32_t vd = vbs
                    + (ks * 16 + (lane & 7) + ((lane >> 3) & 1) * 8) * QROWB
                    + nb * 32 + (lane >> 4) * 16;
                uint32_t r0, r1, r2, r3;
                LDSM4T(r0, r1, r2, r3, vd);
                uint32_t bA[2] = {r0, r1}, bB[2] = {r2, r3};
                MMA_FP(o[nb * 2],     a, bA);
                MMA_FP(o[nb * 2 + 1], a, bB);
            }
        }
        __syncthreads();
    }

    const float inv0 = 1.0f / lacc[0], inv1 = 1.0f / lacc[2];
    const int row0 = b * NQ + q0 + warp * 16 + (lane >> 2);
    const int colb = h * HD + 2 * (lane & 3);
    #pragma unroll
    for (int j = 0; j < 8; j++) {
        const int c = colb + 8 * j;
        *(__half2*)(ao + (size_t)row0 * INNER + c) =
            __floats2half2_rn(o[j][0] * inv0, o[j][1] * inv0);
        *(__half2*)(ao + (size_t)(row0 + 8) * INNER + c) =
            __floats2half2_rn(o[j][2] * inv1, o[j][3] * inv1);
    }
}

// ===========================================================================
// Launch
// ===========================================================================
extern "C" void kernel_launch(void* const* d_in, const int* in_sizes, int n_in,
                              void* d_out, int out_size)
{
    const float* x       = (const float*)d_in[0];
    const float* context = (const float*)d_in[1];
    const float* Wq      = (const float*)d_in[2];
    const float* Wkv     = (const float*)d_in[3];
    const float* Wo      = (const float*)d_in[4];
    const float* bo      = (const float*)d_in[5];
    float* out = (float*)d_out;

    __half *qhp, *kvhp, *aop;
    __half *xh, *ch, *wqt, *wkvt, *wot;
    cudaGetSymbolAddress((void**)&qhp,  g_qh);
    cudaGetSymbolAddress((void**)&kvhp, g_kvh);
    cudaGetSymbolAddress((void**)&aop,  g_ao);
    cudaGetSymbolAddress((void**)&xh,   g_xh);    cudaGetSymbolAddress((void**)&ch,   g_ch);
    cudaGetSymbolAddress((void**)&wqt,  g_wqt);   cudaGetSymbolAddress((void**)&wkvt, g_wkvt);
    cudaGetSymbolAddress((void**)&wot,  g_wot);

    cudaFuncSetAttribute(gemm_qkv16, cudaFuncAttributeMaxDynamicSharedMemorySize, SM16_TOT);
    cudaFuncSetAttribute(gemm_out16, cudaFuncAttributeMaxDynamicSharedMemorySize, SM16_TOT);
    cudaFuncSetAttribute(attn_mma,   cudaFuncAttributeMaxDynamicSharedMemorySize, ATT_SMEM);

    // ---- all conversions in one launch ----
    conv_all<<<8192 + 1024, 256>>>(x, xh, context, ch, Wq, Wkv, Wo,
                                   wqt, wkvt, wot);

    // ---- fused q + kv projections ----
    gemm_qkv16<<<dim3(INNER / 128 + KV_W / 128, MROWS / 128), 256, SM16_TOT>>>(
        xh, ch, wqt, wkvt, qhp, kvhp);

    // ---- attention ----
    attn_mma<<<dim3(NQ / 128, B_ * H_), 256, ATT_SMEM>>>(qhp, kvhp, aop);

    // ---- out = ao @ Wo + bo ----
    gemm_out16<<<dim3(D_ / 128, MROWS / 128), 256, SM16_TOT>>>(
        aop, wot, bo, out);
}

// round 15
// speedup vs baseline: 1.0786x; 1.0786x over previous
#include <cuda_runtime.h>
#include <cuda_fp16.h>
#include <cstdint>

// ===========================================================================
// Problem constants
// ===========================================================================
#define B_    8
#define NQ    1024
#define NK    1024
#define D_    512
#define H_    8
#define HD    64
#define INNER 512
#define KV_W  1024
#define SCALE 0.125f
#define LOG2E 1.44269504f
#define MROWS (B_ * NQ)          // 8192

// ===========================================================================
// Scratch (__device__ globals)
// ===========================================================================
__device__ __align__(16) __half g_qh [MROWS * INNER];
__device__ __align__(16) __half g_kvh[MROWS * KV_W];
__device__ __align__(16) __half g_ao [MROWS * INNER];

__device__ __align__(16) __half g_xh [MROWS * D_];
__device__ __align__(16) __half g_ch [MROWS * D_];
__device__ __align__(16) __half g_wqt [INNER * D_];
__device__ __align__(16) __half g_wkvt[KV_W * D_];
__device__ __align__(16) __half g_wot [D_ * INNER];

// ===========================================================================
// PTX helpers (compute_103-safe)
// ===========================================================================
__device__ __forceinline__ uint32_t smem_u32(const void* p) {
    uint32_t a;
    asm("{ .reg .u64 t; cvta.to.shared.u64 t, %1; cvt.u32.u64 %0, t; }"
        : "=r"(a) : "l"(p));
    return a;
}
#define CP16(dst_u32, src_ptr) \
    asm volatile("cp.async.cg.shared.global [%0], [%1], 16;" \
                 :: "r"(dst_u32), "l"(src_ptr) : "memory")
#define CP_COMMIT() asm volatile("cp.async.commit_group;" ::: "memory")
#define CP_WAIT(n)  asm volatile("cp.async.wait_group %0;" :: "n"(n) : "memory")

#define LDSM4(r0, r1, r2, r3, addr) \
    asm volatile("ldmatrix.sync.aligned.m8n8.x4.shared.b16 {%0,%1,%2,%3}, [%4];" \
                 : "=r"(r0), "=r"(r1), "=r"(r2), "=r"(r3) : "r"(addr))
#define LDSM4T(r0, r1, r2, r3, addr) \
    asm volatile("ldmatrix.sync.aligned.m8n8.x4.trans.shared.b16 {%0,%1,%2,%3}, [%4];" \
                 : "=r"(r0), "=r"(r1), "=r"(r2), "=r"(r3) : "r"(addr))

#define MMA_FP(d, a, b) \
    asm volatile("mma.sync.aligned.m16n8k16.row.col.f32.f16.f16.f32 " \
                 "{%0,%1,%2,%3},{%4,%5,%6,%7},{%8,%9},{%0,%1,%2,%3};" \
                 : "+f"((d)[0]), "+f"((d)[1]), "+f"((d)[2]), "+f"((d)[3]) \
                 : "r"((a)[0]), "r"((a)[1]), "r"((a)[2]), "r"((a)[3]), \
                   "r"((b)[0]), "r"((b)[1]))

#define H2EX2(d, s) \
    asm("ex2.approx.f16x2 %0, %1;" : "=r"(d) : "r"(s))

__device__ __forceinline__ uint32_t pack_h2(float lo, float hi) {
    const __half2 h = __floats2half2_rn(lo, hi);
    return *(const uint32_t*)&h;
}

// ===========================================================================
// Common tile constants
// ===========================================================================
#define KC    32
#define ROWB  80
#define ARR_B (128 * ROWB)             // 10240
#define STG16_B  (2 * ARR_B)           // 20480
#define SM16_TOT (3 * STG16_B)         // 61440 (3-stage; regs cap CTAs anyway)

// ===========================================================================
// Plain fp16 GEMM core, 3-stage cp.async, ONE __syncthreads per K-chunk.
// MODE 0: fp32 out + bias.  MODE 1: fp16 out * oscale.
// ===========================================================================
template <int MODE>
__device__ __forceinline__ void gemm16_core(
    const __half* __restrict__ A, const __half* __restrict__ B,
    const float* __restrict__ bias, void* __restrict__ Cout,
    int N, int K, int m0, int n0, float oscale, char* sm)
{
    const uint32_t sb = smem_u32(sm);
    const int tid = threadIdx.x, lane = tid & 31, warp = tid >> 5;
    const int wm = (warp >> 2) * 64, wn = (warp & 3) * 32;

    const int ldrow = tid >> 1;
    const int ldcb  = (tid & 1) * 32;

    auto stage_load = [&](int s, int k0) {
        const uint32_t so = (uint32_t)(s * STG16_B + ldrow * ROWB + ldcb);
        const size_t ga = ((size_t)(m0 + ldrow) * K + k0) * 2 + ldcb;
        const size_t gb = ((size_t)(n0 + ldrow) * K + k0) * 2 + ldcb;
        CP16(sb + so,              (const char*)A + ga);
        CP16(sb + so + 16,         (const char*)A + ga + 16);
        CP16(sb + so + ARR_B,      (const char*)B + gb);
        CP16(sb + so + ARR_B + 16, (const char*)B + gb + 16);
    };

    float acc[4][4][4] = {};
    const int nch = K / KC;
    stage_load(0, 0);
    CP_COMMIT();
    stage_load(1, KC);
    CP_COMMIT();

    int sbuf = 0, spre = 2;
    for (int ch = 0; ch < nch; ch++) {
        if (ch + 1 < nch) { CP_WAIT(1); } else { CP_WAIT(0); }
        __syncthreads();                    // buf sbuf ready CTA-wide; buf spre
                                            // fully consumed (used at ch-1)
        if (ch + 2 < nch) {
            stage_load(spre, (ch + 2) * KC);
            CP_COMMIT();
        }

        const uint32_t abase = sb + sbuf * STG16_B;
        const uint32_t bbase = abase + ARR_B;

        #pragma unroll
        for (int ks = 0; ks < 2; ks++) {
            const int kb = ks * 32;

            uint32_t af[4][4];
            const uint32_t arow = (uint32_t)(wm + (lane & 15));
            const uint32_t akb  = (uint32_t)(kb + (lane >> 4) * 16);
            #pragma unroll
            for (int mi = 0; mi < 4; mi++) {
                const uint32_t ad = abase + (arow + mi * 16) * ROWB + akb;
                LDSM4(af[mi][0], af[mi][1], af[mi][2], af[mi][3], ad);
            }

            uint32_t bf[4][2];
            const uint32_t brow = (uint32_t)(wn + (lane & 7) + ((lane >> 4) & 1) * 8);
            const uint32_t bkb  = (uint32_t)(kb + ((lane >> 3) & 1) * 16);
            #pragma unroll
            for (int nq = 0; nq < 2; nq++) {
                const uint32_t bd = bbase + (brow + nq * 16) * ROWB + bkb;
                uint32_t r0, r1, r2, r3;
                LDSM4(r0, r1, r2, r3, bd);
                bf[nq * 2][0] = r0; bf[nq * 2][1] = r1;
                bf[nq * 2 + 1][0] = r2; bf[nq * 2 + 1][1] = r3;
            }

            #pragma unroll
            for (int mi = 0; mi < 4; mi++)
                #pragma unroll
                for (int ni = 0; ni < 4; ni++)
                    MMA_FP(acc[mi][ni], af[mi], bf[ni]);
        }

        sbuf = (sbuf + 1 == 3) ? 0 : sbuf + 1;
        spre = (spre + 1 == 3) ? 0 : spre + 1;
    }

    #pragma unroll
    for (int mi = 0; mi < 4; mi++) {
        const int r = m0 + wm + mi * 16 + (lane >> 2);
        #pragma unroll
        for (int ni = 0; ni < 4; ni++) {
            const int c = n0 + wn + ni * 8 + (lane & 3) * 2;
            if (MODE == 0) {
                float* C = (float*)Cout;
                const float2 b2 = *(const float2*)(bias + c);
                *(float2*)(C + (size_t)r * N + c) =
                    make_float2(acc[mi][ni][0] + b2.x, acc[mi][ni][1] + b2.y);
                *(float2*)(C + (size_t)(r + 8) * N + c) =
                    make_float2(acc[mi][ni][2] + b2.x, acc[mi][ni][3] + b2.y);
            } else {
                __half* C = (__half*)Cout;
                *(__half2*)(C + (size_t)r * N + c) =
                    __floats2half2_rn(acc[mi][ni][0] * oscale, acc[mi][ni][1] * oscale);
                *(__half2*)(C + (size_t)(r + 8) * N + c) =
                    __floats2half2_rn(acc[mi][ni][2] * oscale, acc[mi][ni][3] * oscale);
            }
        }
    }
}

// fused q + kv projections
__global__ __launch_bounds__(256) void gemm_qkv16(
    const __half* __restrict__ xh, const __half* __restrict__ ch,
    const __half* __restrict__ wqt, const __half* __restrict__ wkvt,
    __half* __restrict__ qh, __half* __restrict__ kvh)
{
    extern __shared__ char sm[];
    const int m0 = blockIdx.y * 128;
    if (blockIdx.x < INNER / 128)
        gemm16_core<1>(xh, wqt, nullptr, qh, INNER, D_, m0, blockIdx.x * 128,
                       SCALE * LOG2E, sm);
    else
        gemm16_core<1>(ch, wkvt, nullptr, kvh, KV_W, D_, m0,
                       (blockIdx.x - INNER / 128) * 128, 1.0f, sm);
}

// output projection
__global__ __launch_bounds__(256) void gemm_out16(
    const __half* __restrict__ ao, const __half* __restrict__ wot,
    const float* __restrict__ bias, float* __restrict__ C)
{
    extern __shared__ char sm[];
    gemm16_core<0>(ao, wot, bias, C, D_, INNER,
                   blockIdx.y * 128, blockIdx.x * 128, 1.0f, sm);
}

// ===========================================================================
// Fused conversions (one launch): x/context elementwise + 3 weight transposes
// ===========================================================================
__global__ __launch_bounds__(256) void conv_all(
    const float* __restrict__ x, __half* __restrict__ xh,
    const float* __restrict__ ctx, __half* __restrict__ ch,
    const float* __restrict__ Wq, const float* __restrict__ Wkv,
    const float* __restrict__ Wo,
    __half* __restrict__ wqt, __half* __restrict__ wkvt, __half* __restrict__ wot)
{
    const int tid = threadIdx.x;
    int bid = blockIdx.x;
    const int NX4 = MROWS * D_ / 4;
    if (bid < 8192) {
        const bool second = bid >= 4096;
        const float* in = second ? ctx : x;
        __half* outp = second ? ch : xh;
        const int i = (second ? bid - 4096 : bid) * 256 + tid;
        if (i < NX4) {
            const float4 v = *((const float4*)in + i);
            __half h[4];
            h[0] = __float2half_rn(v.x); h[1] = __float2half_rn(v.y);
            h[2] = __float2half_rn(v.z); h[3] = __float2half_rn(v.w);
            *((uint2*)outp + i) = *(const uint2*)h;
        }
        return;
    }
    bid -= 8192;
    __shared__ float t[32][33];
    const int tx = tid & 31, ty = tid >> 5;
    const float* W; __half* WT; int K, N, rel;
    if (bid < 256)      { W = Wq;  WT = wqt;  K = D_;    N = INNER; rel = bid; }
    else if (bid < 768) { W = Wkv; WT = wkvt; K = D_;    N = KV_W;  rel = bid - 256; }
    else                { W = Wo;  WT = wot;  K = INNER; N = D_;    rel = bid - 768; }
    const int nbx = N / 32;
    const int c0 = (rel % nbx) * 32, r0 = (rel / nbx) * 32;

    #pragma unroll
    for (int j = 0; j < 4; j++)
        t[ty + 8 * j][tx] = W[(size_t)(r0 + ty + 8 * j) * N + c0 + tx];
    __syncthreads();
    #pragma unroll
    for (int j = 0; j < 4; j++)
        WT[(size_t)(c0 + ty + 8 * j) * K + r0 + tx] =
            __float2half_rn(t[tx][ty + 8 * j]);
}

// ===========================================================================
// Tensor-core flash attention — exact R13 version (best measured: 58.2us).
// 128 q-rows, 8 warps, Q frags cached, fp16x2 exp, ones-MMA row sums.
// ===========================================================================
#define QROWB 144
#define QS_B  (128 * QROWB)
#define KVSTG (2 * 64 * QROWB)
#define ATT_SMEM (QS_B + 2 * KVSTG)

__global__ __launch_bounds__(256) void attn_mma(
    const __half* __restrict__ qh, const __half* __restrict__ kvh,
    __half* __restrict__ ao)
{
    extern __shared__ char sm[];
    const uint32_t sb = smem_u32(sm);
    const int tid = threadIdx.x, lane = tid & 31, warp = tid >> 5;
    const int bh = blockIdx.y, b = bh >> 3, h = bh & 7;
    const int q0 = blockIdx.x * 128;

    #pragma unroll
    for (int r = 0; r < 4; r++) {
        const int cid = tid + r * 256;
        const int row = cid >> 3, ck = cid & 7;
        const char* src = (const char*)(qh + (size_t)(b * NQ + q0 + row) * INNER + h * HD) + ck * 16;
        CP16(sb + row * QROWB + ck * 16, src);
    }
    CP_COMMIT();

    const __half* kbase = kvh + (size_t)(b * NK) * KV_W + h * HD;
    const __half* vbase = kbase + INNER;
    auto kv_stage = [&](int s, int t) {
        const uint32_t so = sb + QS_B + s * KVSTG;
        #pragma unroll
        for (int r = 0; r < 2; r++) {
            const int cid = tid + r * 256;
            const int row = cid >> 3, ck = cid & 7;
            const size_t go = ((size_t)(t * 64 + row) * KV_W + ck * 8) * 2;
            CP16(so + row * QROWB + ck * 16,              (const char*)kbase + go);
            CP16(so + 64 * QROWB + row * QROWB + ck * 16, (const char*)vbase + go);
        }
    };
    kv_stage(0, 0);
    CP_COMMIT();

    CP_WAIT(1);
    __syncthreads();
    uint32_t qf[4][4];
    {
        const uint32_t qb = sb + warp * 16 * QROWB;
        #pragma unroll
        for (int ks = 0; ks < 4; ks++) {
            const uint32_t ad = qb + (lane & 15) * QROWB + ks * 32 + (lane >> 4) * 16;
            LDSM4(qf[ks][0], qf[ks][1], qf[ks][2], qf[ks][3], ad);
        }
    }

    const uint32_t ONES2 = 0x3C003C00u;
    uint32_t onesf[2] = {ONES2, ONES2};

    float o[8][4] = {};
    float lacc[4] = {};

    for (int t = 0; t < 16; t++) {
        if (t + 1 < 16) {
            kv_stage((t + 1) & 1, t + 1);
            CP_COMMIT();
            CP_WAIT(1);
        } else {
            CP_WAIT(0);
        }
        __syncthreads();

        const uint32_t kbs = sb + QS_B + (t & 1) * KVSTG;
        const uint32_t vbs = kbs + 64 * QROWB;

        float s[8][4] = {};
        #pragma unroll
        for (int ks = 0; ks < 4; ks++) {
            #pragma unroll
            for (int nq = 0; nq < 4; nq++) {
                const uint32_t bd = kbs
                    + (nq * 16 + (lane & 7) + ((lane >> 4) & 1) * 8) * QROWB
                    + ks * 32 + ((lane >> 3) & 1) * 16;
                uint32_t r0, r1, r2, r3;
                LDSM4(r0, r1, r2, r3, bd);
                uint32_t bA[2] = {r0, r1}, bB[2] = {r2, r3};
                MMA_FP(s[nq * 2],     qf[ks], bA);
                MMA_FP(s[nq * 2 + 1], qf[ks], bB);
            }
        }

        uint32_t p[8][2];
        #pragma unroll
        for (int j = 0; j < 8; j++) {
            uint32_t t0 = pack_h2(s[j][0], s[j][1]);
            uint32_t t1 = pack_h2(s[j][2], s[j][3]);
            H2EX2(p[j][0], t0);
            H2EX2(p[j][1], t1);
        }

        #pragma unroll
        for (int ks = 0; ks < 4; ks++) {
            uint32_t a[4];
            a[0] = p[2 * ks][0];
            a[1] = p[2 * ks][1];
            a[2] = p[2 * ks + 1][0];
            a[3] = p[2 * ks + 1][1];
            MMA_FP(lacc, a, onesf);
            #pragma unroll
            for (int nb = 0; nb < 4; nb++) {
                const uint32_t vd = vbs
                    + (ks * 16 + (lane & 7) + ((lane >> 3) & 1) * 8) * QROWB
                    + nb * 32 + (lane >> 4) * 16;
                uint32_t r0, r1, r2, r3;
                LDSM4T(r0, r1, r2, r3, vd);
                uint32_t bA[2] = {r0, r1}, bB[2] = {r2, r3};
                MMA_FP(o[nb * 2],     a, bA);
                MMA_FP(o[nb * 2 + 1], a, bB);
            }
        }
        __syncthreads();
    }

    const float inv0 = 1.0f / lacc[0], inv1 = 1.0f / lacc[2];
    const int row0 = b * NQ + q0 + warp * 16 + (lane >> 2);
    const int colb = h * HD + 2 * (lane & 3);
    #pragma unroll
    for (int j = 0; j < 8; j++) {
        const int c = colb + 8 * j;
        *(__half2*)(ao + (size_t)row0 * INNER + c) =
            __floats2half2_rn(o[j][0] * inv0, o[j][1] * inv0);
        *(__half2*)(ao + (size_t)(row0 + 8) * INNER + c) =
            __floats2half2_rn(o[j][2] * inv1, o[j][3] * inv1);
    }
}

// ===========================================================================
// Launch
// ===========================================================================
extern "C" void kernel_launch(void* const* d_in, const int* in_sizes, int n_in,
                              void* d_out, int out_size)
{
    const float* x       = (const float*)d_in[0];
    const float* context = (const float*)d_in[1];
    const float* Wq      = (const float*)d_in[2];
    const float* Wkv     = (const float*)d_in[3];
    const float* Wo      = (const float*)d_in[4];
    const float* bo      = (const float*)d_in[5];
    float* out = (float*)d_out;

    __half *qhp, *kvhp, *aop;
    __half *xh, *ch, *wqt, *wkvt, *wot;
    cudaGetSymbolAddress((void**)&qhp,  g_qh);
    cudaGetSymbolAddress((void**)&kvhp, g_kvh);
    cudaGetSymbolAddress((void**)&aop,  g_ao);
    cudaGetSymbolAddress((void**)&xh,   g_xh);    cudaGetSymbolAddress((void**)&ch,   g_ch);
    cudaGetSymbolAddress((void**)&wqt,  g_wqt);   cudaGetSymbolAddress((void**)&wkvt, g_wkvt);
    cudaGetSymbolAddress((void**)&wot,  g_wot);

    cudaFuncSetAttribute(gemm_qkv16, cudaFuncAttributeMaxDynamicSharedMemorySize, SM16_TOT);
    cudaFuncSetAttribute(gemm_out16, cudaFuncAttributeMaxDynamicSharedMemorySize, SM16_TOT);
    cudaFuncSetAttribute(attn_mma,   cudaFuncAttributeMaxDynamicSharedMemorySize, ATT_SMEM);

    // ---- all conversions in one launch ----
    conv_all<<<8192 + 1024, 256>>>(x, xh, context, ch, Wq, Wkv, Wo,
                                   wqt, wkvt, wot);

    // ---- fused q + kv projections ----
    gemm_qkv16<<<dim3(INNER / 128 + KV_W / 128, MROWS / 128), 256, SM16_TOT>>>(
        xh, ch, wqt, wkvt, qhp, kvhp);

    // ---- attention ----
    attn_mma<<<dim3(NQ / 128, B_ * H_), 256, ATT_SMEM>>>(qhp, kvhp, aop);

    // ---- out = ao @ Wo + bo ----
    gemm_out16<<<dim3(D_ / 128, MROWS / 128), 256, SM16_TOT>>>(
        aop, wot, bo, out);
}